// round 7
// baseline (speedup 1.0000x reference)
#include <cuda_runtime.h>
#include <cuda_fp16.h>

#define BATCH 16
#define NN    10000
#define NE    160000
#define INF   19
#define HD    64
#define OUTF  32
#define BN    (BATCH*NN)
#define LNEPS 1e-5f

typedef unsigned long long u64;

// ---------------- scratch (device globals) ----------------
__device__ uint4 g_xh[(size_t)BN*8];          // ping (fp16, 128B/row)
__device__ uint4 g_yh[(size_t)BN*8];          // pong (fp16)
__device__ __align__(16) int g_cnt[BN];
__device__ __align__(16) int g_rowptr[BN];
__device__ __align__(16) int g_cursor[BN];
__device__ int   g_csr[(size_t)BATCH*NE];
__device__ int   g_is64;

// ---------------- packed helpers ----------------
__device__ __forceinline__ u64 pk(float x) {
    u64 r; asm("mov.b64 %0,{%1,%1};" : "=l"(r) : "f"(x)); return r;
}
__device__ __forceinline__ void fma2(u64& d, u64 a, u64 b) {
    asm("fma.rn.f32x2 %0,%1,%2,%0;" : "+l"(d) : "l"(a), "l"(b));
}
__device__ __forceinline__ void add2(u64& d, u64 a) {
    asm("add.rn.f32x2 %0,%0,%1;" : "+l"(d) : "l"(a));
}
__device__ __forceinline__ void mul2(u64& d, u64 a) {
    asm("mul.rn.f32x2 %0,%0,%1;" : "+l"(d) : "l"(a));
}
__device__ __forceinline__ void upk(u64 v, float& lo, float& hi) {
    asm("mov.b64 {%0,%1},%2;" : "=f"(lo), "=f"(hi) : "l"(v));
}
__device__ __forceinline__ void addh2(u64& acc, unsigned h) {
    __half2 hh = *(__half2*)&h;
    float2 f = __half22float2(hh);
    u64 p; asm("mov.b64 %0,{%1,%2};" : "=l"(p) : "f"(f.x), "f"(f.y));
    add2(acc, p);
}
__device__ __forceinline__ void acc8(u64* acc, uint4 A) {
    addh2(acc[0], A.x); addh2(acc[1], A.y); addh2(acc[2], A.z); addh2(acc[3], A.w);
}
__device__ __forceinline__ unsigned f2h2(float a, float b) {
    __half2 h = __floats2half2_rn(a, b);
    return *(unsigned*)&h;
}
__device__ __forceinline__ uint4 h4add(uint4 a, uint4 b) {
    uint4 r; __half2 x, y;
    x = *(__half2*)&a.x; y = *(__half2*)&b.x; x = __hadd2(x, y); r.x = *(unsigned*)&x;
    x = *(__half2*)&a.y; y = *(__half2*)&b.y; x = __hadd2(x, y); r.y = *(unsigned*)&x;
    x = *(__half2*)&a.z; y = *(__half2*)&b.z; x = __hadd2(x, y); r.z = *(unsigned*)&x;
    x = *(__half2*)&a.w; y = *(__half2*)&b.w; x = __hadd2(x, y); r.w = *(unsigned*)&x;
    return r;
}
// uint4 of half2 -> 8 floats
__device__ __forceinline__ void h8tof(uint4 v, float* f) {
    float2 a = __half22float2(*(__half2*)&v.x);
    float2 b = __half22float2(*(__half2*)&v.y);
    float2 c = __half22float2(*(__half2*)&v.z);
    float2 d = __half22float2(*(__half2*)&v.w);
    f[0]=a.x; f[1]=a.y; f[2]=b.x; f[3]=b.y; f[4]=c.x; f[5]=c.y; f[6]=d.x; f[7]=d.y;
}

// ---------------- detect + zero, fused ----------------
__global__ void detect_zero_kernel(const int* __restrict__ e) {
    int i = blockIdx.x*256 + threadIdx.x;
    if (i < BN) g_cnt[i] = 0;
    if (blockIdx.x == 0 && threadIdx.x < 32) {
        int nz = 0;
        #pragma unroll
        for (int k = threadIdx.x; k < 128; k += 32) nz |= e[2*k + 1];
        unsigned any = __ballot_sync(0xffffffffu, nz != 0);
        if (threadIdx.x == 0) g_is64 = (any == 0) ? 1 : 0;
    }
}

__global__ __launch_bounds__(256) void hist_kernel(const void* __restrict__ ei) {
    int i = blockIdx.x*256 + threadIdx.x;
    if (i >= BATCH*NE/4) return;
    int is64 = g_is64;
    int i4 = i*4;
    int b = i4 / NE, e = i4 - b*NE;
    int d0, d1, d2, d3;
    if (is64) {
        const longlong2* p = (const longlong2*)((const long long*)ei + (size_t)b*2*NE + NE + e);
        longlong2 v0 = p[0], v1 = p[1];
        d0 = (int)v0.x; d1 = (int)v0.y; d2 = (int)v1.x; d3 = (int)v1.y;
    } else {
        int4 v = *(const int4*)((const int*)ei + (size_t)b*2*NE + NE + e);
        d0 = v.x; d1 = v.y; d2 = v.z; d3 = v.w;
    }
    int* cb = g_cnt + b*NN;
    atomicAdd(cb + d0, 1); atomicAdd(cb + d1, 1);
    atomicAdd(cb + d2, 1); atomicAdd(cb + d3, 1);
}

__global__ void scan_kernel() {
    __shared__ int wsum[32];
    int b = blockIdx.x, t = threadIdx.x, lane = t & 31, w = t >> 5;
    const int4* c4 = (const int4*)(g_cnt + b*NN);
    int4* r4 = (int4*)(g_rowptr + b*NN);
    int4* u4 = (int4*)(g_cursor + b*NN);
    int carry = 0;
    for (int base = 0; base < 2500; base += 1024) {
        int i = base + t;
        int4 v = (i < 2500) ? c4[i] : make_int4(0,0,0,0);
        int t1 = v.x, t2 = t1 + v.y, t3 = t2 + v.z, t4 = t3 + v.w;
        int x = t4;
        #pragma unroll
        for (int o = 1; o < 32; o <<= 1) {
            int y = __shfl_up_sync(0xffffffffu, x, o);
            if (lane >= o) x += y;
        }
        if (lane == 31) wsum[w] = x;
        __syncthreads();
        if (w == 0) {
            int s = wsum[lane];
            #pragma unroll
            for (int o = 1; o < 32; o <<= 1) {
                int y = __shfl_up_sync(0xffffffffu, s, o);
                if (lane >= o) s += y;
            }
            wsum[lane] = s;
        }
        __syncthreads();
        int excl = carry + (w ? wsum[w-1] : 0) + x - t4;
        if (i < 2500) {
            int4 rp = make_int4(excl, excl + t1, excl + t2, excl + t3);
            r4[i] = rp; u4[i] = rp;
        }
        carry += wsum[31];
        __syncthreads();
    }
}

__global__ __launch_bounds__(256) void scatter_kernel(const void* __restrict__ ei) {
    int i = blockIdx.x*256 + threadIdx.x;
    if (i >= BATCH*NE/4) return;
    int is64 = g_is64;
    int i4 = i*4;
    int b = i4 / NE, e = i4 - b*NE;
    int s0, s1, s2, s3, d0, d1, d2, d3;
    if (is64) {
        const longlong2* ps = (const longlong2*)((const long long*)ei + (size_t)b*2*NE + e);
        const longlong2* pd = (const longlong2*)((const long long*)ei + (size_t)b*2*NE + NE + e);
        longlong2 sv0 = ps[0], sv1 = ps[1], dv0 = pd[0], dv1 = pd[1];
        s0 = (int)sv0.x; s1 = (int)sv0.y; s2 = (int)sv1.x; s3 = (int)sv1.y;
        d0 = (int)dv0.x; d1 = (int)dv0.y; d2 = (int)dv1.x; d3 = (int)dv1.y;
    } else {
        int4 sv = *(const int4*)((const int*)ei + (size_t)b*2*NE + e);
        int4 dv = *(const int4*)((const int*)ei + (size_t)b*2*NE + NE + e);
        s0 = sv.x; s1 = sv.y; s2 = sv.z; s3 = sv.w;
        d0 = dv.x; d1 = dv.y; d2 = dv.z; d3 = dv.w;
    }
    int* cur = g_cursor + b*NN;
    int* csr = g_csr + b*NE;
    csr[atomicAdd(cur + d0, 1)] = s0;
    csr[atomicAdd(cur + d1, 1)] = s1;
    csr[atomicAdd(cur + d2, 1)] = s2;
    csr[atomicAdd(cur + d3, 1)] = s3;
}

// ---------------- encoder: x = relu(nf@W1+b1)@W2+b2 -> fp16 rows ----------------
__global__ __launch_bounds__(256) void encode_kernel(
    const float* __restrict__ nf,
    const float* __restrict__ W1, const float* __restrict__ b1,
    const float* __restrict__ W2, const float* __restrict__ b2)
{
    __shared__ float sW1[INF*HD];
    __shared__ float sW2[HD*HD];
    __shared__ float sb1[HD], sb2[HD];
    __shared__ float snf[64*20];
    __shared__ float sh[64*68];
    int t = threadIdx.x;
    for (int i = t; i < INF*HD; i += 256) sW1[i] = W1[i];
    for (int i = t; i < HD*HD;  i += 256) sW2[i] = W2[i];
    if (t < HD) { sb1[t] = b1[t]; sb2[t] = b2[t]; }
    int base = blockIdx.x * 64;
    for (int i = t; i < 64*INF; i += 256) {
        int node = i / INF, k = i - node*INF;
        snf[node*20 + k] = nf[(size_t)(base + node)*INF + k];
    }
    __syncthreads();

    int colg = t & 7, pair = t >> 3;
    int c0 = colg << 3;
    int n0 = pair*2, n1 = n0 + 1;

    u64 p0[4] = {0,0,0,0}, p1[4] = {0,0,0,0};
    for (int k = 0; k < INF; k++) {
        u64 A0 = pk(snf[n0*20 + k]), A1 = pk(snf[n1*20 + k]);
        const ulonglong2* wp = (const ulonglong2*)&sW1[k*HD + c0];
        ulonglong2 wa = wp[0], wb = wp[1];
        fma2(p0[0], A0, wa.x); fma2(p0[1], A0, wa.y); fma2(p0[2], A0, wb.x); fma2(p0[3], A0, wb.y);
        fma2(p1[0], A1, wa.x); fma2(p1[1], A1, wa.y); fma2(p1[2], A1, wb.x); fma2(p1[3], A1, wb.y);
    }
    float h0[8], h1[8];
    #pragma unroll
    for (int j = 0; j < 4; j++) { upk(p0[j], h0[2*j], h0[2*j+1]); upk(p1[j], h1[2*j], h1[2*j+1]); }
    #pragma unroll
    for (int j = 0; j < 8; j++) {
        sh[n0*68 + c0 + j] = fmaxf(h0[j] + sb1[c0+j], 0.f);
        sh[n1*68 + c0 + j] = fmaxf(h1[j] + sb1[c0+j], 0.f);
    }
    __syncthreads();

    #pragma unroll
    for (int j = 0; j < 4; j++) { p0[j] = 0; p1[j] = 0; }
    for (int k = 0; k < HD; k += 4) {
        float4 a0 = *(const float4*)&sh[n0*68 + k];
        float4 a1 = *(const float4*)&sh[n1*68 + k];
        #pragma unroll
        for (int kk = 0; kk < 4; kk++) {
            u64 A0 = pk(((const float*)&a0)[kk]);
            u64 A1 = pk(((const float*)&a1)[kk]);
            const ulonglong2* wp = (const ulonglong2*)&sW2[(k+kk)*HD + c0];
            ulonglong2 wa = wp[0], wb = wp[1];
            fma2(p0[0], A0, wa.x); fma2(p0[1], A0, wa.y); fma2(p0[2], A0, wb.x); fma2(p0[3], A0, wb.y);
            fma2(p1[0], A1, wa.x); fma2(p1[1], A1, wa.y); fma2(p1[2], A1, wb.x); fma2(p1[3], A1, wb.y);
        }
    }
    float y0[8], y1[8];
    #pragma unroll
    for (int j = 0; j < 4; j++) { upk(p0[j], y0[2*j], y0[2*j+1]); upk(p1[j], y1[2*j], y1[2*j+1]); }
    #pragma unroll
    for (int j = 0; j < 8; j++) { y0[j] += sb2[c0+j]; y1[j] += sb2[c0+j]; }

    size_t gn0 = base + n0, gn1 = base + n1;
    g_xh[gn0*8 + colg] = make_uint4(f2h2(y0[0],y0[1]), f2h2(y0[2],y0[3]), f2h2(y0[4],y0[5]), f2h2(y0[6],y0[7]));
    g_xh[gn1*8 + colg] = make_uint4(f2h2(y1[0],y1[1]), f2h2(y1[2],y1[3]), f2h2(y1[4],y1[5]), f2h2(y1[6],y1[7]));
}

// ---------------- fused conv layer: 512 thr, 64 nodes, 8 thr/node ----------------
__global__ __launch_bounds__(512, 2) void conv_kernel(
    int dir,
    const float* __restrict__ W, const float* __restrict__ bias,
    const float* __restrict__ gam, const float* __restrict__ bet,
    const float* __restrict__ Wo, const float* __restrict__ bo,
    float* __restrict__ outp)
{
    const uint4* __restrict__ xinh  = dir ? g_yh : g_xh;
    uint4*       __restrict__ xouth = dir ? g_xh : g_yh;

    extern __shared__ float sm[];
    float* sW    = sm;                 // 128*64 = 8192
    float* scomb = sm + 8192;          // 64*132 = 8448 (x | agg)
    float* sb    = scomb + 8448;
    float* sg    = sb + 64;
    float* sbe   = sg + 64;
    float* sWo   = sbe + 64;           // 64*32
    float* sbo   = sWo + 2048;         // 32

    int t = threadIdx.x;
    #pragma unroll 4
    for (int i = t; i < 8192; i += 512) sW[i] = W[i];
    if (t < 64) { sb[t] = bias[t]; sg[t] = gam[t]; sbe[t] = bet[t]; }
    if (outp) {
        for (int i = t; i < HD*OUTF; i += 512) sWo[i] = Wo[i];
        if (t < OUTF) sbo[t] = bo[t];
    }

    int node = t >> 3;                 // 0..63
    int q    = t & 7;                  // 0..7 (16B slice of row)
    int gn   = blockIdx.x*64 + node;
    int b    = gn / NN;

    // ---- phase A: self + mean-aggregate; each thread: one uint4 (8 feats) per row
    {
        // self (fp16 -> fp32 into scomb)
        uint4 sv = xinh[(size_t)gn*8 + q];
        float sf[8]; h8tof(sv, sf);
        float* cp = &scomb[node*132 + q*8];
        *(float4*)(cp)   = make_float4(sf[0], sf[1], sf[2], sf[3]);
        *(float4*)(cp+4) = make_float4(sf[4], sf[5], sf[6], sf[7]);

        int start = g_rowptr[gn], end = g_cursor[gn];
        const int* csr = g_csr + b*NE;
        const uint4* xh = xinh + (size_t)b*NN*8 + q;
        u64 acc[4] = {0,0,0,0};
        int j = start;
        for (; j + 4 <= end; j += 4) {
            int i0 = csr[j], i1 = csr[j+1], i2 = csr[j+2], i3 = csr[j+3];
            uint4 a = xh[(size_t)i0*8];
            uint4 bb= xh[(size_t)i1*8];
            uint4 c = xh[(size_t)i2*8];
            uint4 d = xh[(size_t)i3*8];
            acc8(acc, h4add(h4add(a, bb), h4add(c, d)));
        }
        if (j + 2 <= end) {
            int i0 = csr[j], i1 = csr[j+1];
            acc8(acc, h4add(xh[(size_t)i0*8], xh[(size_t)i1*8]));
            j += 2;
        }
        if (j < end) {
            acc8(acc, xh[(size_t)csr[j]*8]);
        }
        u64 SC = pk(1.f / fmaxf((float)(end - start), 1.f));
        #pragma unroll
        for (int r = 0; r < 4; r++) mul2(acc[r], SC);
        float* ap = cp + 64;
        *(ulonglong2*)(ap)   = make_ulonglong2(acc[0], acc[1]);
        *(ulonglong2*)(ap+4) = make_ulonglong2(acc[2], acc[3]);
    }
    __syncthreads();

    // ---- phase B: y = combined@W; epilogue bias+residual+LN+relu (1 node x 8 cols)
    int c0 = q << 3;
    const float* cb = &scomb[node*132];

    u64 p[4] = {0,0,0,0};
    for (int k = 0; k < 128; k += 4) {
        float4 a = *(const float4*)(cb + k);
        #pragma unroll
        for (int kk = 0; kk < 4; kk++) {
            u64 A = pk(((const float*)&a)[kk]);
            const ulonglong2* wp = (const ulonglong2*)&sW[(k+kk)*HD + c0];
            ulonglong2 wa = wp[0], wb = wp[1];
            fma2(p[0], A, wa.x); fma2(p[1], A, wa.y); fma2(p[2], A, wb.x); fma2(p[3], A, wb.y);
        }
    }

    float y[8];
    #pragma unroll
    for (int j = 0; j < 4; j++) upk(p[j], y[2*j], y[2*j+1]);
    float s0 = 0.f, q0 = 0.f;
    #pragma unroll
    for (int j = 0; j < 8; j++) {
        y[j] += sb[c0+j] + cb[c0+j];
        s0 += y[j]; q0 += y[j]*y[j];
    }
    #pragma unroll
    for (int off = 1; off < 8; off <<= 1) {
        s0 += __shfl_xor_sync(0xffffffffu, s0, off, 8);
        q0 += __shfl_xor_sync(0xffffffffu, q0, off, 8);
    }
    const float invH = 1.f/64.f;
    float mu = s0*invH, var = q0*invH - mu*mu;
    float iv = rsqrtf(var + LNEPS);

    float r[8];
    #pragma unroll
    for (int j = 0; j < 8; j++)
        r[j] = fmaxf((y[j]-mu)*iv*sg[c0+j] + sbe[c0+j], 0.f);

    if (!outp) {
        xouth[(size_t)gn*8 + q] = make_uint4(f2h2(r[0],r[1]), f2h2(r[2],r[3]), f2h2(r[4],r[5]), f2h2(r[6],r[7]));
        return;
    }

    // ---- fused output head: out = r @ Wo + bo
    __syncthreads();
    {
        float* wp = &scomb[node*132 + c0];
        *(float4*)(wp)   = make_float4(r[0], r[1], r[2], r[3]);
        *(float4*)(wp+4) = make_float4(r[4], r[5], r[6], r[7]);
    }
    __syncthreads();

    int c4 = q << 2;                   // 4 output cols per thread
    u64 qp[2] = {0,0};
    const float* x0 = &scomb[node*132];
    for (int k = 0; k < HD; k += 4) {
        float4 a = *(const float4*)(x0 + k);
        #pragma unroll
        for (int kk = 0; kk < 4; kk++) {
            u64 A = pk(((const float*)&a)[kk]);
            ulonglong2 w = *(const ulonglong2*)&sWo[(k+kk)*OUTF + c4];
            fma2(qp[0], A, w.x); fma2(qp[1], A, w.y);
        }
    }
    float z[4];
    upk(qp[0], z[0], z[1]); upk(qp[1], z[2], z[3]);
    *(float4*)(outp + (size_t)gn*OUTF + c4) =
        make_float4(z[0]+sbo[c4], z[1]+sbo[c4+1], z[2]+sbo[c4+2], z[3]+sbo[c4+3]);
}

// ---------------- launch ----------------
extern "C" void kernel_launch(void* const* d_in, const int* in_sizes, int n_in,
                              void* d_out, int out_size) {
    const float* nf     = (const float*)d_in[0];
    const void*  ei     = d_in[1];
    const float* enc_w1 = (const float*)d_in[3];
    const float* enc_b1 = (const float*)d_in[4];
    const float* enc_w2 = (const float*)d_in[5];
    const float* enc_b2 = (const float*)d_in[6];
    const float* conv_w = (const float*)d_in[7];
    const float* conv_b = (const float*)d_in[8];
    const float* ln_g   = (const float*)d_in[9];
    const float* ln_b   = (const float*)d_in[10];
    const float* out_w  = (const float*)d_in[11];
    const float* out_b  = (const float*)d_in[12];
    float* out = (float*)d_out;

    detect_zero_kernel<<<(BN + 255)/256, 256>>>((const int*)ei);
    int eb4 = (BATCH*NE/4 + 255)/256;
    hist_kernel<<<eb4, 256>>>(ei);
    scan_kernel<<<BATCH, 1024>>>();
    scatter_kernel<<<eb4, 256>>>(ei);

    encode_kernel<<<BN/64, 256>>>(nf, enc_w1, enc_b1, enc_w2, enc_b2);

    int convsmem = (8192 + 8448 + 192 + 2048 + 32) * (int)sizeof(float);   // 75648 B
    cudaFuncSetAttribute(conv_kernel, cudaFuncAttributeMaxDynamicSharedMemorySize, convsmem);
    for (int l = 0; l < 3; l++) {
        conv_kernel<<<BN/64, 512, convsmem>>>(l & 1,
            conv_w + (size_t)l*128*64, conv_b + (size_t)l*64,
            ln_g + (size_t)l*64, ln_b + (size_t)l*64,
            out_w, out_b, (l == 2) ? out : nullptr);
    }
}

// round 8
// speedup vs baseline: 1.4434x; 1.4434x over previous
#include <cuda_runtime.h>
#include <cuda_fp16.h>

#define BATCH 16
#define NN    10000
#define NE    160000
#define INF   19
#define HD    64
#define OUTF  32
#define BN    (BATCH*NN)
#define LNEPS 1e-5f

typedef unsigned long long u64;

// ---------------- scratch (device globals; no allocs allowed) ----------------
__device__ float g_x[(size_t)BN*HD];          // ping (fp32)
__device__ float g_y[(size_t)BN*HD];          // pong (fp32)
__device__ uint4 g_xh[(size_t)BN*8];          // ping (fp16 mirror, 128B/row)
__device__ uint4 g_yh[(size_t)BN*8];          // pong (fp16 mirror)
__device__ __align__(16) int g_cnt[BN];
__device__ __align__(16) int g_rowptr[BN];
__device__ __align__(16) int g_cursor[BN];
__device__ int   g_csr[(size_t)BATCH*NE];
__device__ int   g_is64;

// ---------------- packed f32x2 helpers ----------------
__device__ __forceinline__ u64 pk(float x) {
    u64 r; asm("mov.b64 %0,{%1,%1};" : "=l"(r) : "f"(x)); return r;
}
__device__ __forceinline__ void fma2(u64& d, u64 a, u64 b) {
    asm("fma.rn.f32x2 %0,%1,%2,%0;" : "+l"(d) : "l"(a), "l"(b));
}
__device__ __forceinline__ void add2(u64& d, u64 a) {
    asm("add.rn.f32x2 %0,%0,%1;" : "+l"(d) : "l"(a));
}
__device__ __forceinline__ void mul2(u64& d, u64 a) {
    asm("mul.rn.f32x2 %0,%0,%1;" : "+l"(d) : "l"(a));
}
__device__ __forceinline__ void upk(u64 v, float& lo, float& hi) {
    asm("mov.b64 {%0,%1},%2;" : "=f"(lo), "=f"(hi) : "l"(v));
}
__device__ __forceinline__ void addh2(u64& acc, unsigned h) {
    __half2 hh = *(__half2*)&h;
    float2 f = __half22float2(hh);
    u64 p; asm("mov.b64 %0,{%1,%2};" : "=l"(p) : "f"(f.x), "f"(f.y));
    add2(acc, p);
}
__device__ __forceinline__ void acc16(u64* acc, uint4 A, uint4 B) {
    addh2(acc[0], A.x); addh2(acc[1], A.y); addh2(acc[2], A.z); addh2(acc[3], A.w);
    addh2(acc[4], B.x); addh2(acc[5], B.y); addh2(acc[6], B.z); addh2(acc[7], B.w);
}
__device__ __forceinline__ unsigned f2h2(float a, float b) {
    __half2 h = __floats2half2_rn(a, b);
    return *(unsigned*)&h;
}
__device__ __forceinline__ uint4 h4add(uint4 a, uint4 b) {
    uint4 r; __half2 x, y;
    x = *(__half2*)&a.x; y = *(__half2*)&b.x; x = __hadd2(x, y); r.x = *(unsigned*)&x;
    x = *(__half2*)&a.y; y = *(__half2*)&b.y; x = __hadd2(x, y); r.y = *(unsigned*)&x;
    x = *(__half2*)&a.z; y = *(__half2*)&b.z; x = __hadd2(x, y); r.z = *(unsigned*)&x;
    x = *(__half2*)&a.w; y = *(__half2*)&b.w; x = __hadd2(x, y); r.w = *(unsigned*)&x;
    return r;
}

// ---------------- detect + zero, fused ----------------
__global__ void detect_zero_kernel(const int* __restrict__ e) {
    int i = blockIdx.x*256 + threadIdx.x;
    if (i < BN) g_cnt[i] = 0;
    if (blockIdx.x == 0 && threadIdx.x < 32) {
        int nz = 0;
        #pragma unroll
        for (int k = threadIdx.x; k < 128; k += 32) nz |= e[2*k + 1];
        unsigned any = __ballot_sync(0xffffffffu, nz != 0);
        if (threadIdx.x == 0) g_is64 = (any == 0) ? 1 : 0;
    }
}

// ---------------- hist: 4 edges per thread ----------------
__global__ __launch_bounds__(256) void hist_kernel(const void* __restrict__ ei) {
    int i = blockIdx.x*256 + threadIdx.x;
    if (i >= BATCH*NE/4) return;
    int is64 = g_is64;
    int i4 = i*4;
    int b = i4 / NE, e = i4 - b*NE;
    int d0, d1, d2, d3;
    if (is64) {
        const longlong2* p = (const longlong2*)((const long long*)ei + (size_t)b*2*NE + NE + e);
        longlong2 v0 = p[0], v1 = p[1];
        d0 = (int)v0.x; d1 = (int)v0.y; d2 = (int)v1.x; d3 = (int)v1.y;
    } else {
        int4 v = *(const int4*)((const int*)ei + (size_t)b*2*NE + NE + e);
        d0 = v.x; d1 = v.y; d2 = v.z; d3 = v.w;
    }
    int* cb = g_cnt + b*NN;
    atomicAdd(cb + d0, 1); atomicAdd(cb + d1, 1);
    atomicAdd(cb + d2, 1); atomicAdd(cb + d3, 1);
}

// int4 scan: 2500 int4 per batch, 3 chunks of 1024, register carry
__global__ void scan_kernel() {
    __shared__ int wsum[32];
    int b = blockIdx.x, t = threadIdx.x, lane = t & 31, w = t >> 5;
    const int4* c4 = (const int4*)(g_cnt + b*NN);
    int4* r4 = (int4*)(g_rowptr + b*NN);
    int4* u4 = (int4*)(g_cursor + b*NN);
    int carry = 0;
    for (int base = 0; base < 2500; base += 1024) {
        int i = base + t;
        int4 v = (i < 2500) ? c4[i] : make_int4(0,0,0,0);
        int t1 = v.x, t2 = t1 + v.y, t3 = t2 + v.z, t4 = t3 + v.w;
        int x = t4;
        #pragma unroll
        for (int o = 1; o < 32; o <<= 1) {
            int y = __shfl_up_sync(0xffffffffu, x, o);
            if (lane >= o) x += y;
        }
        if (lane == 31) wsum[w] = x;
        __syncthreads();
        if (w == 0) {
            int s = wsum[lane];
            #pragma unroll
            for (int o = 1; o < 32; o <<= 1) {
                int y = __shfl_up_sync(0xffffffffu, s, o);
                if (lane >= o) s += y;
            }
            wsum[lane] = s;
        }
        __syncthreads();
        int excl = carry + (w ? wsum[w-1] : 0) + x - t4;
        if (i < 2500) {
            int4 rp = make_int4(excl, excl + t1, excl + t2, excl + t3);
            r4[i] = rp; u4[i] = rp;
        }
        carry += wsum[31];
        __syncthreads();
    }
}

// ---------------- scatter: 4 edges per thread ----------------
__global__ __launch_bounds__(256) void scatter_kernel(const void* __restrict__ ei) {
    int i = blockIdx.x*256 + threadIdx.x;
    if (i >= BATCH*NE/4) return;
    int is64 = g_is64;
    int i4 = i*4;
    int b = i4 / NE, e = i4 - b*NE;
    int s0, s1, s2, s3, d0, d1, d2, d3;
    if (is64) {
        const longlong2* ps = (const longlong2*)((const long long*)ei + (size_t)b*2*NE + e);
        const longlong2* pd = (const longlong2*)((const long long*)ei + (size_t)b*2*NE + NE + e);
        longlong2 sv0 = ps[0], sv1 = ps[1], dv0 = pd[0], dv1 = pd[1];
        s0 = (int)sv0.x; s1 = (int)sv0.y; s2 = (int)sv1.x; s3 = (int)sv1.y;
        d0 = (int)dv0.x; d1 = (int)dv0.y; d2 = (int)dv1.x; d3 = (int)dv1.y;
    } else {
        int4 sv = *(const int4*)((const int*)ei + (size_t)b*2*NE + e);
        int4 dv = *(const int4*)((const int*)ei + (size_t)b*2*NE + NE + e);
        s0 = sv.x; s1 = sv.y; s2 = sv.z; s3 = sv.w;
        d0 = dv.x; d1 = dv.y; d2 = dv.z; d3 = dv.w;
    }
    int* cur = g_cursor + b*NN;
    int* csr = g_csr + b*NE;
    csr[atomicAdd(cur + d0, 1)] = s0;
    csr[atomicAdd(cur + d1, 1)] = s1;
    csr[atomicAdd(cur + d2, 1)] = s2;
    csr[atomicAdd(cur + d3, 1)] = s3;
}

// ---------------- encoder: x = relu(nf@W1+b1)@W2+b2; writes fp32 + fp16 mirror ----------------
__global__ __launch_bounds__(256) void encode_kernel(
    const float* __restrict__ nf,
    const float* __restrict__ W1, const float* __restrict__ b1,
    const float* __restrict__ W2, const float* __restrict__ b2)
{
    __shared__ float sW1[INF*HD];
    __shared__ float sW2[HD*HD];
    __shared__ float sb1[HD], sb2[HD];
    __shared__ float snf[64*20];
    __shared__ float sh[64*68];
    int t = threadIdx.x;
    for (int i = t; i < INF*HD; i += 256) sW1[i] = W1[i];
    for (int i = t; i < HD*HD;  i += 256) sW2[i] = W2[i];
    if (t < HD) { sb1[t] = b1[t]; sb2[t] = b2[t]; }
    int base = blockIdx.x * 64;
    for (int i = t; i < 64*INF; i += 256) {
        int node = i / INF, k = i - node*INF;
        snf[node*20 + k] = nf[(size_t)(base + node)*INF + k];
    }
    __syncthreads();

    int colg = t & 7, pair = t >> 3;
    int c0 = colg << 3;
    int n0 = pair*2, n1 = n0 + 1;

    u64 p0[4] = {0,0,0,0}, p1[4] = {0,0,0,0};
    for (int k = 0; k < INF; k++) {
        u64 A0 = pk(snf[n0*20 + k]), A1 = pk(snf[n1*20 + k]);
        const ulonglong2* wp = (const ulonglong2*)&sW1[k*HD + c0];
        ulonglong2 wa = wp[0], wb = wp[1];
        fma2(p0[0], A0, wa.x); fma2(p0[1], A0, wa.y); fma2(p0[2], A0, wb.x); fma2(p0[3], A0, wb.y);
        fma2(p1[0], A1, wa.x); fma2(p1[1], A1, wa.y); fma2(p1[2], A1, wb.x); fma2(p1[3], A1, wb.y);
    }
    float h0[8], h1[8];
    #pragma unroll
    for (int j = 0; j < 4; j++) { upk(p0[j], h0[2*j], h0[2*j+1]); upk(p1[j], h1[2*j], h1[2*j+1]); }
    #pragma unroll
    for (int j = 0; j < 8; j++) {
        sh[n0*68 + c0 + j] = fmaxf(h0[j] + sb1[c0+j], 0.f);
        sh[n1*68 + c0 + j] = fmaxf(h1[j] + sb1[c0+j], 0.f);
    }
    __syncthreads();

    #pragma unroll
    for (int j = 0; j < 4; j++) { p0[j] = 0; p1[j] = 0; }
    for (int k = 0; k < HD; k += 4) {
        float4 a0 = *(const float4*)&sh[n0*68 + k];
        float4 a1 = *(const float4*)&sh[n1*68 + k];
        #pragma unroll
        for (int kk = 0; kk < 4; kk++) {
            u64 A0 = pk(((const float*)&a0)[kk]);
            u64 A1 = pk(((const float*)&a1)[kk]);
            const ulonglong2* wp = (const ulonglong2*)&sW2[(k+kk)*HD + c0];
            ulonglong2 wa = wp[0], wb = wp[1];
            fma2(p0[0], A0, wa.x); fma2(p0[1], A0, wa.y); fma2(p0[2], A0, wb.x); fma2(p0[3], A0, wb.y);
            fma2(p1[0], A1, wa.x); fma2(p1[1], A1, wa.y); fma2(p1[2], A1, wb.x); fma2(p1[3], A1, wb.y);
        }
    }
    float y0[8], y1[8];
    #pragma unroll
    for (int j = 0; j < 4; j++) { upk(p0[j], y0[2*j], y0[2*j+1]); upk(p1[j], y1[2*j], y1[2*j+1]); }
    #pragma unroll
    for (int j = 0; j < 8; j++) { y0[j] += sb2[c0+j]; y1[j] += sb2[c0+j]; }

    size_t gn0 = base + n0, gn1 = base + n1;
    float* o0 = g_x + gn0*HD + c0;
    float* o1 = g_x + gn1*HD + c0;
    *(float4*)(o0)   = make_float4(y0[0], y0[1], y0[2], y0[3]);
    *(float4*)(o0+4) = make_float4(y0[4], y0[5], y0[6], y0[7]);
    *(float4*)(o1)   = make_float4(y1[0], y1[1], y1[2], y1[3]);
    *(float4*)(o1+4) = make_float4(y1[4], y1[5], y1[6], y1[7]);
    g_xh[gn0*8 + colg] = make_uint4(f2h2(y0[0],y0[1]), f2h2(y0[2],y0[3]), f2h2(y0[4],y0[5]), f2h2(y0[6],y0[7]));
    g_xh[gn1*8 + colg] = make_uint4(f2h2(y1[0],y1[1]), f2h2(y1[2],y1[3]), f2h2(y1[4],y1[5]), f2h2(y1[6],y1[7]));
}

// ---------------- fused conv layer (+ optional fused output head), 3 blocks/SM ----------------
__global__ __launch_bounds__(256, 3) void conv_kernel(
    int dir,
    const float* __restrict__ W, const float* __restrict__ bias,
    const float* __restrict__ gam, const float* __restrict__ bet,
    const float* __restrict__ Wo, const float* __restrict__ bo,
    float* __restrict__ outp)
{
    const float* __restrict__ xin  = dir ? g_y  : g_x;
    const uint4* __restrict__ xinh = dir ? g_yh : g_xh;
    float*       __restrict__ xout = dir ? g_x  : g_y;
    uint4*       __restrict__ xouth= dir ? g_xh : g_yh;

    extern __shared__ float sm[];
    float* sW    = sm;                 // 128*64
    float* scomb = sm + 8192;          // 64*132
    float* sb    = scomb + 8448;
    float* sg    = sb + 64;
    float* sbe   = sg + 64;
    float* sWo   = sbe + 64;           // 64*32
    float* sbo   = sWo + 2048;         // 32

    int t = threadIdx.x;
    #pragma unroll 4
    for (int i = t; i < 8192; i += 256) sW[i] = W[i];
    if (t < 64) { sb[t] = bias[t]; sg[t] = gam[t]; sbe[t] = bet[t]; }
    if (outp) {
        for (int i = t; i < HD*OUTF; i += 256) sWo[i] = Wo[i];
        if (t < OUTF) sbo[t] = bo[t];
    }

    // ---- phase A: self (fp32) + mean-aggregate (fp16 tree-4 + fp32 acc), 4 thr/node
    {
        int node = t >> 2;
        int q = t & 3;
        int gn = blockIdx.x*64 + node;
        int b = gn / NN;
        int start = g_rowptr[gn], end = g_cursor[gn];

        const float4* xr = (const float4*)(xin + (size_t)gn*HD) + q*4;
        float4 s0 = xr[0], s1 = xr[1], s2 = xr[2], s3 = xr[3];
        float* cp = &scomb[node*132 + q*16];
        *(float4*)(cp)    = s0;
        *(float4*)(cp+4)  = s1;
        *(float4*)(cp+8)  = s2;
        *(float4*)(cp+12) = s3;

        const int* csr = g_csr + b*NE;
        const uint4* xh = xinh + (size_t)b*NN*8 + q*2;   // row = 8 uint4
        u64 acc[8] = {0,0,0,0,0,0,0,0};
        int j = start;
        for (; j + 4 <= end; j += 4) {
            int i0 = csr[j], i1 = csr[j+1], i2 = csr[j+2], i3 = csr[j+3];
            uint4 a0 = xh[i0*8], a1 = xh[i0*8 + 1];
            uint4 b0 = xh[i1*8], b1 = xh[i1*8 + 1];
            uint4 c0v= xh[i2*8], c1 = xh[i2*8 + 1];
            uint4 d0 = xh[i3*8], d1 = xh[i3*8 + 1];
            uint4 t0 = h4add(h4add(a0, b0), h4add(c0v, d0));   // depth-2 fp16 tree
            uint4 t1 = h4add(h4add(a1, b1), h4add(c1, d1));
            acc16(acc, t0, t1);                                 // fp32 accumulate
        }
        if (j + 2 <= end) {
            int i0 = csr[j], i1 = csr[j+1];
            uint4 a0 = xh[i0*8], a1 = xh[i0*8 + 1];
            uint4 b0 = xh[i1*8], b1 = xh[i1*8 + 1];
            acc16(acc, h4add(a0, b0), h4add(a1, b1));
            j += 2;
        }
        if (j < end) {
            int i0 = csr[j];
            acc16(acc, xh[i0*8], xh[i0*8 + 1]);
        }
        u64 SC = pk(1.f / fmaxf((float)(end - start), 1.f));
        #pragma unroll
        for (int r = 0; r < 8; r++) mul2(acc[r], SC);
        float* ap = cp + 64;
        *(ulonglong2*)(ap)    = make_ulonglong2(acc[0], acc[1]);
        *(ulonglong2*)(ap+4)  = make_ulonglong2(acc[2], acc[3]);
        *(ulonglong2*)(ap+8)  = make_ulonglong2(acc[4], acc[5]);
        *(ulonglong2*)(ap+12) = make_ulonglong2(acc[6], acc[7]);
    }
    __syncthreads();

    // ---- phase B: y = combined@W (f32x2); epilogue bias+residual+LN+relu
    int colg = t & 7, pair = t >> 3;
    int c0 = colg << 3;
    int n0 = pair*2, n1 = n0 + 1;
    const float* cb0 = &scomb[n0*132];
    const float* cb1 = &scomb[n1*132];

    u64 p0[4] = {0,0,0,0}, p1[4] = {0,0,0,0};
    for (int k = 0; k < 128; k += 4) {
        float4 a0 = *(const float4*)(cb0 + k);
        float4 a1 = *(const float4*)(cb1 + k);
        #pragma unroll
        for (int kk = 0; kk < 4; kk++) {
            u64 A0 = pk(((const float*)&a0)[kk]);
            u64 A1 = pk(((const float*)&a1)[kk]);
            const ulonglong2* wp = (const ulonglong2*)&sW[(k+kk)*HD + c0];
            ulonglong2 wa = wp[0], wb = wp[1];
            fma2(p0[0], A0, wa.x); fma2(p0[1], A0, wa.y); fma2(p0[2], A0, wb.x); fma2(p0[3], A0, wb.y);
            fma2(p1[0], A1, wa.x); fma2(p1[1], A1, wa.y); fma2(p1[2], A1, wb.x); fma2(p1[3], A1, wb.y);
        }
    }

    float y0[8], y1[8];
    #pragma unroll
    for (int j = 0; j < 4; j++) { upk(p0[j], y0[2*j], y0[2*j+1]); upk(p1[j], y1[2*j], y1[2*j+1]); }
    float s0 = 0.f, q0 = 0.f, s1 = 0.f, q1 = 0.f;
    #pragma unroll
    for (int j = 0; j < 8; j++) {
        y0[j] += sb[c0+j] + cb0[c0+j];
        y1[j] += sb[c0+j] + cb1[c0+j];
        s0 += y0[j]; q0 += y0[j]*y0[j];
        s1 += y1[j]; q1 += y1[j]*y1[j];
    }
    #pragma unroll
    for (int off = 1; off < 8; off <<= 1) {
        s0 += __shfl_xor_sync(0xffffffffu, s0, off, 8);
        q0 += __shfl_xor_sync(0xffffffffu, q0, off, 8);
        s1 += __shfl_xor_sync(0xffffffffu, s1, off, 8);
        q1 += __shfl_xor_sync(0xffffffffu, q1, off, 8);
    }
    const float invH = 1.f/64.f;
    float mu0 = s0*invH, var0 = q0*invH - mu0*mu0;
    float mu1 = s1*invH, var1 = q1*invH - mu1*mu1;
    float iv0 = rsqrtf(var0 + LNEPS);
    float iv1 = rsqrtf(var1 + LNEPS);

    float r0[8], r1[8];
    #pragma unroll
    for (int j = 0; j < 8; j++) {
        r0[j] = fmaxf((y0[j]-mu0)*iv0*sg[c0+j] + sbe[c0+j], 0.f);
        r1[j] = fmaxf((y1[j]-mu1)*iv1*sg[c0+j] + sbe[c0+j], 0.f);
    }

    size_t gn0 = (size_t)blockIdx.x*64 + n0, gn1 = gn0 + 1;
    if (!outp) {
        float* o0 = xout + gn0*HD + c0;
        float* o1 = xout + gn1*HD + c0;
        *(float4*)(o0)   = make_float4(r0[0], r0[1], r0[2], r0[3]);
        *(float4*)(o0+4) = make_float4(r0[4], r0[5], r0[6], r0[7]);
        *(float4*)(o1)   = make_float4(r1[0], r1[1], r1[2], r1[3]);
        *(float4*)(o1+4) = make_float4(r1[4], r1[5], r1[6], r1[7]);
        xouth[gn0*8 + colg] = make_uint4(f2h2(r0[0],r0[1]), f2h2(r0[2],r0[3]), f2h2(r0[4],r0[5]), f2h2(r0[6],r0[7]));
        xouth[gn1*8 + colg] = make_uint4(f2h2(r1[0],r1[1]), f2h2(r1[2],r1[3]), f2h2(r1[4],r1[5]), f2h2(r1[6],r1[7]));
        return;
    }

    // ---- fused output head: out = r @ Wo + bo
    __syncthreads();
    {
        float* w0p = &scomb[n0*132 + c0];
        float* w1p = &scomb[n1*132 + c0];
        *(float4*)(w0p)   = make_float4(r0[0], r0[1], r0[2], r0[3]);
        *(float4*)(w0p+4) = make_float4(r0[4], r0[5], r0[6], r0[7]);
        *(float4*)(w1p)   = make_float4(r1[0], r1[1], r1[2], r1[3]);
        *(float4*)(w1p+4) = make_float4(r1[4], r1[5], r1[6], r1[7]);
    }
    __syncthreads();

    int c4 = colg << 2;
    u64 q0p[2] = {0,0}, q1p[2] = {0,0};
    const float* x0 = &scomb[n0*132];
    const float* x1 = &scomb[n1*132];
    for (int k = 0; k < HD; k += 4) {
        float4 a0 = *(const float4*)(x0 + k);
        float4 a1 = *(const float4*)(x1 + k);
        #pragma unroll
        for (int kk = 0; kk < 4; kk++) {
            u64 A0 = pk(((const float*)&a0)[kk]);
            u64 A1 = pk(((const float*)&a1)[kk]);
            ulonglong2 w = *(const ulonglong2*)&sWo[(k+kk)*OUTF + c4];
            fma2(q0p[0], A0, w.x); fma2(q0p[1], A0, w.y);
            fma2(q1p[0], A1, w.x); fma2(q1p[1], A1, w.y);
        }
    }
    float z0[4], z1[4];
    upk(q0p[0], z0[0], z0[1]); upk(q0p[1], z0[2], z0[3]);
    upk(q1p[0], z1[0], z1[1]); upk(q1p[1], z1[2], z1[3]);
    float4 o0 = make_float4(z0[0]+sbo[c4], z0[1]+sbo[c4+1], z0[2]+sbo[c4+2], z0[3]+sbo[c4+3]);
    float4 o1 = make_float4(z1[0]+sbo[c4], z1[1]+sbo[c4+1], z1[2]+sbo[c4+2], z1[3]+sbo[c4+3]);
    *(float4*)(outp + gn0*OUTF + c4) = o0;
    *(float4*)(outp + gn1*OUTF + c4) = o1;
}

// ---------------- launch ----------------
extern "C" void kernel_launch(void* const* d_in, const int* in_sizes, int n_in,
                              void* d_out, int out_size) {
    const float* nf     = (const float*)d_in[0];
    const void*  ei     = d_in[1];
    const float* enc_w1 = (const float*)d_in[3];
    const float* enc_b1 = (const float*)d_in[4];
    const float* enc_w2 = (const float*)d_in[5];
    const float* enc_b2 = (const float*)d_in[6];
    const float* conv_w = (const float*)d_in[7];
    const float* conv_b = (const float*)d_in[8];
    const float* ln_g   = (const float*)d_in[9];
    const float* ln_b   = (const float*)d_in[10];
    const float* out_w  = (const float*)d_in[11];
    const float* out_b  = (const float*)d_in[12];
    float* out = (float*)d_out;

    detect_zero_kernel<<<(BN + 255)/256, 256>>>((const int*)ei);
    int eb4 = (BATCH*NE/4 + 255)/256;
    hist_kernel<<<eb4, 256>>>(ei);
    scan_kernel<<<BATCH, 1024>>>();
    scatter_kernel<<<eb4, 256>>>(ei);

    encode_kernel<<<BN/64, 256>>>(nf, enc_w1, enc_b1, enc_w2, enc_b2);

    int convsmem = (8192 + 8448 + 192 + 2048 + 32) * (int)sizeof(float);   // 75648 B
    cudaFuncSetAttribute(conv_kernel, cudaFuncAttributeMaxDynamicSharedMemorySize, convsmem);
    for (int l = 0; l < 3; l++) {
        conv_kernel<<<BN/64, 256, convsmem>>>(l & 1,
            conv_w + (size_t)l*128*64, conv_b + (size_t)l*64,
            ln_g + (size_t)l*64, ln_b + (size_t)l*64,
            out_w, out_b, (l == 2) ? out : nullptr);
    }
}